// round 17
// baseline (speedup 1.0000x reference)
#include <cuda_runtime.h>
#include <cuda_fp16.h>
#include <math.h>
#include <stdint.h>

#define D      128
#define TILE   128
#define NTHR   256
#define MAXN   51200

// ---------------------------------------------------------------------------
// Static device scratch (no cudaMalloc allowed)
// ---------------------------------------------------------------------------
__device__ float    g_agg[(size_t)MAXN * D];   // scatter-add target
__device__ uint32_t g_Bh[4][8192];             // fp16 W images, uint4-packed frag order
// 0 = We1, 1 = We2, 2 = Wu1, 3 = Wu2  (32 KB each)

__device__ __forceinline__ uint32_t h2pack(float lo, float hi) {
    __half2 h = __floats2half2_rn(lo, hi);
    return *reinterpret_cast<uint32_t*>(&h);
}

__device__ __forceinline__ float gelu_exact(float v) {
    return 0.5f * v * (1.0f + erff(v * 0.70710678118654752f));
}

// streaming load: do NOT allocate in L1 (protects x rows + B images in L1)
__device__ __forceinline__ float4 ldg_stream(const float4* p) {
    float4 v;
    asm("ld.global.nc.L1::no_allocate.v4.f32 {%0,%1,%2,%3}, [%4];"
        : "=f"(v.x), "=f"(v.y), "=f"(v.z), "=f"(v.w) : "l"(p));
    return v;
}

// group barrier: 128 threads, named barrier id (1 or 2)
__device__ __forceinline__ void bar_group(int id) {
    asm volatile("bar.sync %0, 128;" :: "r"(id) : "memory");
}

__device__ __forceinline__ void mma_f16(float* c,
                                        uint32_t a0, uint32_t a1, uint32_t a2, uint32_t a3,
                                        uint32_t b0, uint32_t b1) {
    asm volatile(
        "mma.sync.aligned.m16n8k16.row.col.f32.f16.f16.f32 "
        "{%0,%1,%2,%3}, {%4,%5,%6,%7}, {%8,%9}, {%0,%1,%2,%3};"
        : "+f"(c[0]), "+f"(c[1]), "+f"(c[2]), "+f"(c[3])
        : "r"(a0), "r"(a1), "r"(a2), "r"(a3), "r"(b0), "r"(b1));
}

__device__ __forceinline__ void red_add_v4(float* p, float4 v) {
    asm volatile("red.global.add.v4.f32 [%0], {%1,%2,%3,%4};"
                 :: "l"(p), "f"(v.x), "f"(v.y), "f"(v.z), "f"(v.w) : "memory");
}

// ---------------------------------------------------------------------------
// prep: W[k][n] -> fp16 m16n8k16 B-fragment order, uint4-packed.
// ---------------------------------------------------------------------------
__global__ void prep_weights(const float* __restrict__ We1, const float* __restrict__ We2,
                             const float* __restrict__ Wu1, const float* __restrict__ Wu2)
{
    int id = blockIdx.x * blockDim.x + threadIdx.x;
    if (id >= 4 * 4096) return;
    int m = id >> 12, r = id & 4095;
    int ca = r >> 8, s = (r >> 5) & 7, lane = r & 31;
    int g = lane >> 2, t = lane & 3;
    const float* W = (m == 0) ? We1 : (m == 1) ? We2 : (m == 2) ? Wu1 : Wu2;
    int n = ca * 8 + g;
    int k0 = 16 * s + 2 * t;
    uint32_t b0 = h2pack(W[k0 * D + n],       W[(k0 + 1) * D + n]);
    uint32_t b1 = h2pack(W[(k0 + 8) * D + n], W[(k0 + 9) * D + n]);
    int idx = ((ca * 4 + (s >> 1)) * 32 + lane) * 4 + (s & 1) * 2;
    g_Bh[m][idx]     = b0;
    g_Bh[m][idx + 1] = b1;
}

__global__ void zero_agg(size_t nd)
{
    size_t i = ((size_t)blockIdx.x * blockDim.x + threadIdx.x) * 4;
    size_t stride = (size_t)gridDim.x * blockDim.x * 4;
    float4 z = make_float4(0.f, 0.f, 0.f, 0.f);
    for (; i < nd; i += stride) *(float4*)(g_agg + i) = z;
}

// dummy: keeps ncu's -s 5 capture on the EDGE kernel
__global__ void slot_pad() {}

// ---------------------------------------------------------------------------
// 64(rows)x32(cols)x128 GEMM slice per warp (fp16, m16n8k16);
// A fragment-major smem (LDS.128), B uint4 frags from L1-resident global.
// ---------------------------------------------------------------------------
__device__ __forceinline__ void do_gemm(const uint4* __restrict__ F,
                                        const uint4* __restrict__ Bq,
                                        int ra0, int lane,
                                        float acc[4][4][4])
{
    #pragma unroll
    for (int r = 0; r < 4; ++r)
        #pragma unroll
        for (int ca = 0; ca < 4; ++ca)
            #pragma unroll
            for (int q = 0; q < 4; ++q) acc[r][ca][q] = 0.f;

    #pragma unroll
    for (int sp = 0; sp < 4; ++sp) {
        int s0 = sp * 2, s1 = s0 + 1;
        uint4 a0[4], a1[4];
        #pragma unroll
        for (int r = 0; r < 4; ++r) {
            a0[r] = F[((ra0 + r) * 8 + s0) * 33 + lane];
            a1[r] = F[((ra0 + r) * 8 + s1) * 33 + lane];
        }
        #pragma unroll
        for (int ca = 0; ca < 4; ++ca) {
            uint4 b = __ldg(Bq + (ca * 4 + sp) * 32);
            #pragma unroll
            for (int r = 0; r < 4; ++r) {
                mma_f16(acc[r][ca], a0[r].x, a0[r].y, a0[r].z, a0[r].w, b.x, b.y);
                mma_f16(acc[r][ca], a1[r].x, a1[r].y, a1[r].z, a1[r].w, b.z, b.w);
            }
        }
    }
}

// ---------------------------------------------------------------------------
// Fused 2-layer MLP on a 128-row tile (fp16 MMA). Two INDEPENDENT 64-row
// half-pipelines per CTA (group = wm): each group of 4 warps gathers, GEMMs,
// and GELUs its own 64 rows, synchronized by 128-thread named barriers.
// Full-CTA syncs only bracket the short linear-overlay + output tail.
// A frags: u4 [0,2112) (group wm owns atoms wm*4..+3); H frags: [2112,4224).
// EDGE: A = x[src]+ea -> MLP -> smem-recoalesced red.v4 into g_agg[dst]
// NODE: A = (1+eps)*x + g_agg -> MLP -> out
// ---------------------------------------------------------------------------
template <bool EDGE>
__global__ void __launch_bounds__(NTHR, 2) fused_mlp_mma(
    const float* __restrict__ x,
    const int*   __restrict__ src,
    const int*   __restrict__ dst,
    const float* __restrict__ ea,
    const float* __restrict__ b1,
    const float* __restrict__ b2,
    const float* __restrict__ eps,
    float*       __restrict__ out,
    int count)
{
    extern __shared__ float Asf[];                 // 16896 floats = 4224 uint4
    uint4*    As4  = (uint4*)Asf;                  // A frags [0,2112)
    uint4*    Hs4  = As4 + 2112;                   // H frags [2112,4224)
    uint32_t* As32 = (uint32_t*)Asf;

    const int tid  = threadIdx.x;
    const int lane = tid & 31, wid = tid >> 5;
    const int wm = wid & 1, wn = wid >> 1;         // 2 row-groups x 4 col-groups
    const int g = lane >> 2, t = lane & 3;
    const int r0 = blockIdx.x * TILE;
    const int imgbase = EDGE ? 0 : 2;
    const int barid = 1 + wm;

    // ---- gather (own group's 64 rows): warp instr = 4 rows x 128B ----
    {
        const int o   = lane & 7;          // 128B octant within row
        const int rg  = lane >> 3;         // row within warp's 4-row slice
        const int kq  = o & 3, sb = o >> 2;
        const int aX2 = (kq >> 1) * 2;
        const int t0  = (kq & 1) * 2;
        const float oe = EDGE ? 0.f : (1.0f + eps[0]);

        #pragma unroll
        for (int p = 0; p < 4; ++p) {
            const int lrow = wm * 64 + wn * 4 + rg + 16 * p;   // own group rows
            const int row  = r0 + lrow;
            const bool v   = row < count;

            const float* px = nullptr;
            const float* pe = nullptr;
            if (EDGE) {
                if (v) { px = x + (size_t)__ldg(&src[row]) * D; pe = ea + (size_t)row * D; }
            } else {
                if (v) { px = x + (size_t)row * D; pe = g_agg + (size_t)row * D; }
            }
            const int atom = lrow >> 4, g_g = lrow & 7, rh = (lrow >> 3) & 1;

            #pragma unroll
            for (int c = 0; c < 4; ++c) {
                float f0 = 0.f, f1 = 0.f, f2 = 0.f, f3 = 0.f;
                if (v) {
                    int col = 32 * c + 4 * o;
                    float4 xa  = __ldg((const float4*)(px + col));
                    float4 eaa = ldg_stream((const float4*)(pe + col));
                    if (EDGE) {
                        f0 = xa.x + eaa.x; f1 = xa.y + eaa.y;
                        f2 = xa.z + eaa.z; f3 = xa.w + eaa.w;
                    } else {
                        f0 = fmaf(oe, xa.x, eaa.x); f1 = fmaf(oe, xa.y, eaa.y);
                        f2 = fmaf(oe, xa.z, eaa.z); f3 = fmaf(oe, xa.w, eaa.w);
                    }
                }
                int s = 2 * c + sb;
                uint32_t idx = (uint32_t)((atom * 8 + s) * 33 + g_g * 4 + t0) * 4 + aX2 + rh;
                As32[idx]     = h2pack(f0, f1);
                As32[idx + 4] = h2pack(f2, f3);
            }
        }
    }
    bar_group(barid);                              // own group's A frags ready

    const uint4* Bq1 = (const uint4*)&g_Bh[imgbase][0]     + wn * 512 + lane;
    const uint4* Bq2 = (const uint4*)&g_Bh[imgbase + 1][0] + wn * 512 + lane;
    const int ra0 = wm * 4;

    float acc[4][4][4];

    // ---- GEMM1 (reads own group's A frags) ----
    do_gemm(As4, Bq1, ra0, lane, acc);
    // no barrier: H goes to its own buffer

    // ---- epilogue1: H = GELU(C + b1) -> Hs4 (own group atoms) ----
    #pragma unroll
    for (int p = 0; p < 2; ++p) {
        int sH = wn * 2 + p;
        int ca0 = 2 * p, ca1 = 2 * p + 1;
        int cb0 = wn * 32 + ca0 * 8 + 2 * t;
        int cb1 = wn * 32 + ca1 * 8 + 2 * t;
        float b00 = __ldg(&b1[cb0]), b01 = __ldg(&b1[cb0 + 1]);
        float b10 = __ldg(&b1[cb1]), b11 = __ldg(&b1[cb1 + 1]);
        #pragma unroll
        for (int ma = 0; ma < 4; ++ma) {
            uint4 f;
            f.x = h2pack(gelu_exact(acc[ma][ca0][0] + b00), gelu_exact(acc[ma][ca0][1] + b01));
            f.y = h2pack(gelu_exact(acc[ma][ca0][2] + b00), gelu_exact(acc[ma][ca0][3] + b01));
            f.z = h2pack(gelu_exact(acc[ma][ca1][0] + b10), gelu_exact(acc[ma][ca1][1] + b11));
            f.w = h2pack(gelu_exact(acc[ma][ca1][2] + b10), gelu_exact(acc[ma][ca1][3] + b11));
            Hs4[((ra0 + ma) * 8 + sH) * 33 + lane] = f;
        }
    }
    bar_group(barid);                              // own group's H frags ready

    // ---- GEMM2 (reads own group's H frags) ----
    do_gemm(Hs4, Bq2, ra0, lane, acc);
    __syncthreads();   // FULL: linear overlay spans both groups' frag buffers

    // ---- epilogue2: raw C2 -> linear smem (fp32, own group rows) ----
    #pragma unroll
    for (int ca = 0; ca < 4; ++ca) {
        int col = wn * 32 + ca * 8 + 2 * t;
        #pragma unroll
        for (int ma = 0; ma < 4; ++ma) {
            int row = wm * 64 + ma * 16 + g;
            *(float2*)(Asf + row * 132 + col)       = make_float2(acc[ma][ca][0], acc[ma][ca][1]);
            *(float2*)(Asf + (row + 8) * 132 + col) = make_float2(acc[ma][ca][2], acc[ma][ca][3]);
        }
    }
    __syncthreads();

    // ---- output (own group rows): coalesced + bias ----
    {
        int c4 = lane * 4;
        float4 bias = *(const float4*)&b2[c4];
        int rbase = wm * 64 + wn * 16;
        #pragma unroll
        for (int i = 0; i < 16; ++i) {
            int r = rbase + i;
            int row = r0 + r;
            if (row < count) {
                float4 v = *(float4*)(Asf + r * 132 + c4);
                v.x += bias.x; v.y += bias.y; v.z += bias.z; v.w += bias.w;
                if (EDGE) {
                    int dn = __ldg(&dst[row]);
                    red_add_v4(g_agg + (size_t)dn * D + c4, v);
                } else {
                    *(float4*)(out + (size_t)row * D + c4) = v;
                }
            }
        }
    }
}

// ---------------------------------------------------------------------------
// Inputs: x, edge_index(int32 [2,E]), edge_attr, We1, be1, We2, be2,
//         Wu1, bu1, Wu2, bu2, eps
// ---------------------------------------------------------------------------
extern "C" void kernel_launch(void* const* d_in, const int* in_sizes, int n_in,
                              void* d_out, int out_size)
{
    const float* x   = (const float*)d_in[0];
    const int*   ei  = (const int*)d_in[1];
    const float* ea  = (const float*)d_in[2];
    const float* We1 = (const float*)d_in[3];
    const float* be1 = (const float*)d_in[4];
    const float* We2 = (const float*)d_in[5];
    const float* be2 = (const float*)d_in[6];
    const float* Wu1 = (const float*)d_in[7];
    const float* bu1 = (const float*)d_in[8];
    const float* Wu2 = (const float*)d_in[9];
    const float* bu2 = (const float*)d_in[10];
    const float* eps = (const float*)d_in[11];
    float*       out = (float*)d_out;

    const int N = in_sizes[0] / D;
    const int E = in_sizes[1] / 2;
    const int* src = ei;
    const int* dst = ei + E;

    const int SMEM_BYTES = 16896 * 4;   // 67584 — A+H frag / linear overlay, 2 CTAs/SM
    cudaFuncSetAttribute(fused_mlp_mma<true>,  cudaFuncAttributeMaxDynamicSharedMemorySize, SMEM_BYTES);
    cudaFuncSetAttribute(fused_mlp_mma<false>, cudaFuncAttributeMaxDynamicSharedMemorySize, SMEM_BYTES);

    prep_weights<<<64, 256>>>(We1, We2, Wu1, Wu2);
    zero_agg<<<1024, 256>>>((size_t)N * D);
    slot_pad<<<1, 32>>>();   // keeps ncu -s 5 capture on the edge kernel

    int eblocks = (E + TILE - 1) / TILE;
    fused_mlp_mma<true><<<eblocks, NTHR, SMEM_BYTES>>>(x, src, dst, ea, be1, be2, eps, out, E);

    int nblocks = (N + TILE - 1) / TILE;
    fused_mlp_mma<false><<<nblocks, NTHR, SMEM_BYTES>>>(x, src, dst, ea, bu1, bu2, eps, out, N);
}